// round 17
// baseline (speedup 1.0000x reference)
#include <cuda_runtime.h>
#include <cuda_bf16.h>
#include <math.h>

#define MAXN 50000
#define MAXE 600000
#define HID 128
#define NGRAPH 64

// ---------------- scratch (static device globals) ----------------
__device__ __nv_bfloat16 g_xb[(size_t)MAXN * HID];
__device__ __nv_bfloat16 g_yb[(size_t)MAXN * HID];
__device__ __nv_bfloat16 g_h0b[(size_t)MAXN * HID];
__device__ int   g_cnt[MAXN + 1];
__device__ int   g_off[MAXN + 1];
__device__ int   g_fill[MAXN];
__device__ int   g_srcs[MAXE];
__device__ int   g_bsum[64];
__device__ float g_pooled[NGRAPH * HID];
__device__ __nv_bfloat16 g_wt[128 * 768];

// ---------------- tiny helpers ----------------
__device__ __forceinline__ void cpa16(unsigned dst, const void* src, int pbytes) {
    asm volatile("cp.async.cg.shared.global [%0], [%1], 16, %2;\n"
                 :: "r"(dst), "l"(src), "r"(pbytes));
}
__device__ __forceinline__ void cpa_commit() { asm volatile("cp.async.commit_group;\n"); }
__device__ __forceinline__ void cpa_wait0()  { asm volatile("cp.async.wait_group 0;\n"); }
__device__ __forceinline__ void cpa_wait1()  { asm volatile("cp.async.wait_group 1;\n"); }

__device__ __forceinline__ void mma16816(float c[4], const unsigned a[4], const unsigned* b) {
    asm volatile(
        "mma.sync.aligned.m16n8k16.row.col.f32.bf16.bf16.f32 "
        "{%0,%1,%2,%3},{%4,%5,%6,%7},{%8,%9},{%0,%1,%2,%3};"
        : "+f"(c[0]), "+f"(c[1]), "+f"(c[2]), "+f"(c[3])
        : "r"(a[0]), "r"(a[1]), "r"(a[2]), "r"(a[3]), "r"(b[0]), "r"(b[1]));
}
__device__ __forceinline__ void ldsm_x4(unsigned r[4], unsigned addr) {
    asm volatile("ldmatrix.sync.aligned.m8n8.x4.shared.b16 {%0,%1,%2,%3}, [%4];"
                 : "=r"(r[0]), "=r"(r[1]), "=r"(r[2]), "=r"(r[3]) : "r"(addr));
}

// ---------------- conversion kernels ----------------
__global__ void wconvert_all(const float* __restrict__ w0, const float* __restrict__ wa0,
                             const float* __restrict__ w1, const float* __restrict__ wa1,
                             __nv_bfloat16* __restrict__ wt)
{
    const int r = blockIdx.y;
    const int K   = (r & 1) ? 256 : 128;
    const int off = (r == 0) ? 0 : (r == 1) ? 16384 : (r == 2) ? 49152 : 65536;
    const float* W = (r == 0) ? w0 : (r == 1) ? wa0 : (r == 2) ? w1 : wa1;
    int idx = blockIdx.x * blockDim.x + threadIdx.x;
    if (idx >= 128 * K) return;
    int n = idx / K, k = idx % K;
    wt[off + idx] = __float2bfloat16(W[(size_t)k * 128 + n]);
}

__global__ void xconvert_kernel(const float* __restrict__ x,
                                __nv_bfloat16* __restrict__ xb, int total4)
{
    int i = blockIdx.x * blockDim.x + threadIdx.x;
    if (i >= total4) return;
    float4 v = *(const float4*)(x + (size_t)i * 4);
    __nv_bfloat162 p0(__float2bfloat16(v.x), __float2bfloat16(v.y));
    __nv_bfloat162 p1(__float2bfloat16(v.z), __float2bfloat16(v.w));
    *(__nv_bfloat162*)(xb + (size_t)i * 4)     = p0;
    *(__nv_bfloat162*)(xb + (size_t)i * 4 + 2) = p1;
}

// ---------------- CSR build ----------------
__global__ void zero_kernel(int* cnt, float* pooled, int ncnt, int npool) {
    int i = blockIdx.x * blockDim.x + threadIdx.x;
    if (i < ncnt)  cnt[i] = 0;
    if (i < npool) pooled[i] = 0.0f;
}
__global__ void hist_kernel(const int* __restrict__ dst, int* __restrict__ cnt, int E) {
    int e = blockIdx.x * blockDim.x + threadIdx.x;
    if (e < E) atomicAdd(&cnt[dst[e]], 1);
}
__global__ void scan1_kernel(const int* __restrict__ cnt, int* __restrict__ bsum, int Ntot) {
    __shared__ int ws[32];
    int i = blockIdx.x * 1024 + threadIdx.x;
    int v = (i < Ntot) ? cnt[i] : 0;
    #pragma unroll
    for (int d = 16; d > 0; d >>= 1) v += __shfl_down_sync(0xffffffffu, v, d);
    if ((threadIdx.x & 31) == 0) ws[threadIdx.x >> 5] = v;
    __syncthreads();
    if (threadIdx.x < 32) {
        int s = ws[threadIdx.x];
        #pragma unroll
        for (int d = 16; d > 0; d >>= 1) s += __shfl_down_sync(0xffffffffu, s, d);
        if (threadIdx.x == 0) bsum[blockIdx.x] = s;
    }
}
__global__ void scan2_kernel(int* __restrict__ bsum, int nb) {
    int tid = threadIdx.x;
    int v0 = (tid < nb) ? bsum[tid] : 0;
    int v1 = (tid + 32 < nb) ? bsum[tid + 32] : 0;
    int x = v0;
    #pragma unroll
    for (int d = 1; d < 32; d <<= 1) {
        int t = __shfl_up_sync(0xffffffffu, x, d);
        if (tid >= d) x += t;
    }
    int total0 = __shfl_sync(0xffffffffu, x, 31);
    int y = v1;
    #pragma unroll
    for (int d = 1; d < 32; d <<= 1) {
        int t = __shfl_up_sync(0xffffffffu, y, d);
        if (tid >= d) y += t;
    }
    if (tid < nb) bsum[tid] = x - v0;
    if (tid + 32 < nb) bsum[tid + 32] = total0 + y - v1;
}
__global__ void scan3_kernel(const int* __restrict__ cnt, const int* __restrict__ bsum,
                             int* __restrict__ off, int* __restrict__ fill, int Ntot, int N) {
    __shared__ int ws[32];
    int i = blockIdx.x * 1024 + threadIdx.x;
    int tid = threadIdx.x;
    int v = (i < Ntot) ? cnt[i] : 0;
    int x = v;
    #pragma unroll
    for (int d = 1; d < 32; d <<= 1) {
        int t = __shfl_up_sync(0xffffffffu, x, d);
        if ((tid & 31) >= d) x += t;
    }
    if ((tid & 31) == 31) ws[tid >> 5] = x;
    __syncthreads();
    if (tid < 32) {
        int w = ws[tid];
        #pragma unroll
        for (int d = 1; d < 32; d <<= 1) {
            int t = __shfl_up_sync(0xffffffffu, w, d);
            if (tid >= d) w += t;
        }
        ws[tid] = w;
    }
    __syncthreads();
    int warpOff = (tid >= 32) ? ws[(tid >> 5) - 1] : 0;
    int excl = bsum[blockIdx.x] + warpOff + x - v;
    if (i < Ntot) {
        off[i] = excl;
        if (i < N) fill[i] = excl;
    }
}
__global__ void fill_kernel(const int* __restrict__ src, const int* __restrict__ dst,
                            int* __restrict__ fill, int* __restrict__ srcs, int E) {
    int e = blockIdx.x * blockDim.x + threadIdx.x;
    if (e < E) {
        int p = atomicAdd(&fill[dst[e]], 1);
        srcs[p] = src[e];
    }
}

// ---------------- GEMM kernels ----------------
#define APAD 72
#define STG_ELEMS (2 * 128 * APAD)
#define POOL_SPAN 4
#define SMEM_GEMM (2 * STG_ELEMS * 2 + 1024 + POOL_SPAN * 128 * 4)

__device__ __forceinline__ void stage_W64(const __nv_bfloat16* __restrict__ wt,
                                          int Ktot, int kg, unsigned sbase, int tid) {
    #pragma unroll
    for (int p = 0; p < 4; ++p) {
        int idx = p * 256 + tid;
        int n = idx >> 3, seg = idx & 7;
        cpa16(sbase + (128 * APAD + n * APAD + seg * 8) * 2,
              wt + (size_t)n * Ktot + kg + seg * 8, 16);
    }
}
__device__ __forceinline__ void stage_A64(const __nv_bfloat16* __restrict__ A,
                                          int kk, unsigned sbase, int rowBase, int M, int tid) {
    #pragma unroll
    for (int p = 0; p < 4; ++p) {
        int idx = p * 256 + tid;
        int row = idx >> 3, seg = idx & 7;
        int g = rowBase + row;
        int pb = (g < M) ? 16 : 0;
        int gc = (g < M) ? g : 0;
        cpa16(sbase + (row * APAD + seg * 8) * 2,
              A + (size_t)gc * 128 + kk + seg * 8, pb);
    }
}

#define COMPUTE_CHUNK(stoff)                                                 \
    do {                                                                     \
        _Pragma("unroll")                                                    \
        for (int k16 = 0; k16 < 4; ++k16) {                                  \
            const unsigned kb = (unsigned)k16 * 32;                          \
            unsigned a0[4], a1[4];                                           \
            ldsm_x4(a0, aAddr0 + (stoff) + kb);                              \
            ldsm_x4(a1, aAddr0 + (stoff) + kb + I16);                        \
            unsigned bh[4][4];                                               \
            _Pragma("unroll")                                                \
            for (int jj = 0; jj < 4; ++jj)                                   \
                ldsm_x4(bh[jj], bAddr0 + (stoff) + kb + (unsigned)jj * I16); \
            _Pragma("unroll")                                                \
            for (int jj = 0; jj < 4; ++jj) {                                 \
                mma16816(acc[0][2 * jj],     a0, &bh[jj][0]);                \
                mma16816(acc[1][2 * jj],     a1, &bh[jj][0]);                \
                mma16816(acc[0][2 * jj + 1], a0, &bh[jj][2]);                \
                mma16816(acc[1][2 * jj + 1], a1, &bh[jj][2]);                \
            }                                                                \
        }                                                                    \
    } while (0)

// Fused: agg(Y) via CSR computed in-kernel forms A chunks 0-1; A2 forms chunks 2-3.
// Plain: Ktot=128, A2 is the input, off/srcs null.
__global__ __launch_bounds__(256, 2)
void gemm_mma(const __nv_bfloat16* __restrict__ Y,
              const __nv_bfloat16* __restrict__ A2,
              const __nv_bfloat16* __restrict__ wt,
              int Ktot, const float* __restrict__ bias,
              __nv_bfloat16* __restrict__ C,
              const int* __restrict__ off, const int* __restrict__ srcs,
              const int* __restrict__ batch, float* __restrict__ pooled,
              int M, int doNorm)
{
    extern __shared__ __align__(16) __nv_bfloat16 smem[];
    float* rowss = (float*)(smem + 2 * STG_ELEMS);
    float* spool = rowss + 256;
    const unsigned sb = (unsigned)__cvta_generic_to_shared(smem);

    const int tid = threadIdx.x;
    const int wid = tid >> 5, lane = tid & 31;
    const int wm = wid & 3, wn = wid >> 2;
    const int g4 = lane >> 2, q = lane & 3;
    const int rowBase = blockIdx.x * 128;

    const int aRow = wm * 32 + (lane & 15);
    const int aCol = (lane & 16) ? 8 : 0;
    const unsigned aAddr0 = sb + (unsigned)(aRow * APAD + aCol) * 2;
    const int bRow = wn * 64 + (lane & 7) + ((lane & 16) ? 8 : 0);
    const int bCol = (lane & 8) ? 8 : 0;
    const unsigned bAddr0 = sb + (unsigned)(128 * APAD + bRow * APAD + bCol) * 2;
    const unsigned I16 = 16 * APAD * 2;
    const unsigned SB = STG_ELEMS * 2;   // stage stride in bytes

    float acc[2][8][4];
    #pragma unroll
    for (int i = 0; i < 2; ++i)
        #pragma unroll
        for (int j = 0; j < 8; ++j)
            #pragma unroll
            for (int v = 0; v < 4; ++v) acc[i][j][v] = 0.0f;

    if (off == nullptr) {
        // ---- plain K=128: stage both chunks upfront, single wait ----
        stage_A64(A2, 0, sb, rowBase, M, tid);
        stage_W64(wt, 128, 0, sb, tid);
        stage_A64(A2, 64, sb + SB, rowBase, M, tid);
        stage_W64(wt, 128, 64, sb + SB, tid);
        cpa_commit();
        cpa_wait0();
        __syncthreads();
        COMPUTE_CHUNK(0u);
        COMPUTE_CHUNK(SB);
    } else {
        // ---- fused agg + K=256 ----
        // stage W chunks 0,1 (group A)
        stage_W64(wt, 256, 0, sb, tid);
        stage_W64(wt, 256, 64, sb + SB, tid);
        cpa_commit();
        // gather-mean 16 rows per warp into A slots of both stage buffers
        {
            const int fco = (lane * 4) & 63;          // feature column within 64-chunk
            const size_t aslot = ((lane & 16) ? (size_t)STG_ELEMS : 0);
            #pragma unroll 1
            for (int t = 0; t < 16; ++t) {
                int row = wid * 16 + t;
                int r = rowBase + row;
                float a0 = 0.f, a1 = 0.f, a2 = 0.f, a3 = 0.f;
                if (r < M) {
                    int e0 = off[r], e1 = off[r + 1];
                    int e = e0;
                    for (; e + 3 < e1; e += 4) {
                        int sA = __ldg(&srcs[e]);
                        int sB2 = __ldg(&srcs[e + 1]);
                        int sC = __ldg(&srcs[e + 2]);
                        int sD = __ldg(&srcs[e + 3]);
                        uint2 hA = *(const uint2*)(Y + (size_t)sA * 128 + lane * 4);
                        uint2 hB = *(const uint2*)(Y + (size_t)sB2 * 128 + lane * 4);
                        uint2 hC = *(const uint2*)(Y + (size_t)sC * 128 + lane * 4);
                        uint2 hD = *(const uint2*)(Y + (size_t)sD * 128 + lane * 4);
                        float2 a, b;
                        a = __bfloat1622float2(*(const __nv_bfloat162*)&hA.x);
                        b = __bfloat1622float2(*(const __nv_bfloat162*)&hA.y);
                        a0 += a.x; a1 += a.y; a2 += b.x; a3 += b.y;
                        a = __bfloat1622float2(*(const __nv_bfloat162*)&hB.x);
                        b = __bfloat1622float2(*(const __nv_bfloat162*)&hB.y);
                        a0 += a.x; a1 += a.y; a2 += b.x; a3 += b.y;
                        a = __bfloat1622float2(*(const __nv_bfloat162*)&hC.x);
                        b = __bfloat1622float2(*(const __nv_bfloat162*)&hC.y);
                        a0 += a.x; a1 += a.y; a2 += b.x; a3 += b.y;
                        a = __bfloat1622float2(*(const __nv_bfloat162*)&hD.x);
                        b = __bfloat1622float2(*(const __nv_bfloat162*)&hD.y);
                        a0 += a.x; a1 += a.y; a2 += b.x; a3 += b.y;
                    }
                    for (; e < e1; ++e) {
                        int sA = __ldg(&srcs[e]);
                        uint2 hA = *(const uint2*)(Y + (size_t)sA * 128 + lane * 4);
                        float2 a = __bfloat1622float2(*(const __nv_bfloat162*)&hA.x);
                        float2 b = __bfloat1622float2(*(const __nv_bfloat162*)&hA.y);
                        a0 += a.x; a1 += a.y; a2 += b.x; a3 += b.y;
                    }
                    float inv = 1.0f / fmaxf((float)(e1 - e0), 1.0f);
                    a0 *= inv; a1 *= inv; a2 *= inv; a3 *= inv;
                }
                __nv_bfloat162 q0(__float2bfloat16(a0), __float2bfloat16(a1));
                __nv_bfloat162 q1(__float2bfloat16(a2), __float2bfloat16(a3));
                __nv_bfloat16* dstp = smem + aslot + (size_t)row * APAD + fco;
                *(__nv_bfloat162*)(dstp)     = q0;
                *(__nv_bfloat162*)(dstp + 2) = q1;
            }
        }
        cpa_wait0();
        __syncthreads();
        COMPUTE_CHUNK(0u);                                 // chunk0: aggA s0, W0
        __syncthreads();
        stage_A64(A2, 0, sb, rowBase, M, tid);             // s0 <- A2 k0..63, W k128..191
        stage_W64(wt, 256, 128, sb, tid);
        cpa_commit();
        COMPUTE_CHUNK(SB);                                 // chunk1: aggA s1, W1
        __syncthreads();
        stage_A64(A2, 64, sb + SB, rowBase, M, tid);       // s1 <- A2 k64..127, W k192..255
        stage_W64(wt, 256, 192, sb + SB, tid);
        cpa_commit();
        cpa_wait1();                                        // s0 group landed
        __syncthreads();
        COMPUTE_CHUNK(0u);                                 // chunk2
        cpa_wait0();
        __syncthreads();
        COMPUTE_CHUNK(SB);                                 // chunk3
    }

    // ---- epilogue: bias + relu (+ norm) ----
    #pragma unroll
    for (int j = 0; j < 8; ++j) {
        int col = wn * 64 + j * 8 + q * 2;
        float2 b = *(const float2*)(bias + col);
        #pragma unroll
        for (int i = 0; i < 2; ++i) {
            acc[i][j][0] = fmaxf(acc[i][j][0] + b.x, 0.0f);
            acc[i][j][1] = fmaxf(acc[i][j][1] + b.y, 0.0f);
            acc[i][j][2] = fmaxf(acc[i][j][2] + b.x, 0.0f);
            acc[i][j][3] = fmaxf(acc[i][j][3] + b.y, 0.0f);
        }
    }
    if (doNorm) {
        __syncthreads();
        #pragma unroll
        for (int i = 0; i < 2; ++i) {
            int r = wm * 32 + i * 16 + g4;
            float ssLo = 0.f, ssHi = 0.f;
            #pragma unroll
            for (int j = 0; j < 8; ++j) {
                ssLo += acc[i][j][0] * acc[i][j][0] + acc[i][j][1] * acc[i][j][1];
                ssHi += acc[i][j][2] * acc[i][j][2] + acc[i][j][3] * acc[i][j][3];
            }
            ssLo += __shfl_xor_sync(0xffffffffu, ssLo, 1);
            ssLo += __shfl_xor_sync(0xffffffffu, ssLo, 2);
            ssHi += __shfl_xor_sync(0xffffffffu, ssHi, 1);
            ssHi += __shfl_xor_sync(0xffffffffu, ssHi, 2);
            if (q == 0) { rowss[r * 2 + wn] = ssLo; rowss[(r + 8) * 2 + wn] = ssHi; }
        }
        __syncthreads();
        #pragma unroll
        for (int i = 0; i < 2; ++i) {
            int r = wm * 32 + i * 16 + g4;
            float invLo = 1.0f / fmaxf(sqrtf(rowss[r * 2] + rowss[r * 2 + 1]), 1e-12f);
            float invHi = 1.0f / fmaxf(sqrtf(rowss[(r + 8) * 2] + rowss[(r + 8) * 2 + 1]), 1e-12f);
            #pragma unroll
            for (int j = 0; j < 8; ++j) {
                acc[i][j][0] *= invLo; acc[i][j][1] *= invLo;
                acc[i][j][2] *= invHi; acc[i][j][3] *= invHi;
            }
        }
    }

    if (pooled) {
        for (int s = tid; s < POOL_SPAN * 128; s += 256) spool[s] = 0.0f;
        __syncthreads();
        const int gLo = batch[rowBase];
        #pragma unroll
        for (int i = 0; i < 2; ++i) {
            int r0 = rowBase + wm * 32 + i * 16 + g4;
            int r1 = r0 + 8;
            int dg0 = (r0 < M) ? (batch[r0] - gLo) : -1;
            int dg1 = (r1 < M) ? (batch[r1] - gLo) : -1;
            #pragma unroll
            for (int j = 0; j < 8; ++j) {
                int col = wn * 64 + j * 8 + q * 2;
                if (dg0 >= 0) {
                    if (dg0 < POOL_SPAN) {
                        atomicMax((int*)&spool[dg0 * 128 + col],     __float_as_int(acc[i][j][0]));
                        atomicMax((int*)&spool[dg0 * 128 + col + 1], __float_as_int(acc[i][j][1]));
                    } else {
                        atomicMax((int*)&pooled[(gLo + dg0) * 128 + col],     __float_as_int(acc[i][j][0]));
                        atomicMax((int*)&pooled[(gLo + dg0) * 128 + col + 1], __float_as_int(acc[i][j][1]));
                    }
                }
                if (dg1 >= 0) {
                    if (dg1 < POOL_SPAN) {
                        atomicMax((int*)&spool[dg1 * 128 + col],     __float_as_int(acc[i][j][2]));
                        atomicMax((int*)&spool[dg1 * 128 + col + 1], __float_as_int(acc[i][j][3]));
                    } else {
                        atomicMax((int*)&pooled[(gLo + dg1) * 128 + col],     __float_as_int(acc[i][j][2]));
                        atomicMax((int*)&pooled[(gLo + dg1) * 128 + col + 1], __float_as_int(acc[i][j][3]));
                    }
                }
            }
        }
        __syncthreads();
        for (int s = tid; s < POOL_SPAN * 128; s += 256) {
            float v = spool[s];
            int gIdx = gLo + (s >> 7);
            if (v > 0.0f && gIdx < NGRAPH)
                atomicMax((int*)&pooled[gIdx * 128 + (s & 127)], __float_as_int(v));
        }
    } else {
        #pragma unroll
        for (int i = 0; i < 2; ++i) {
            int r0 = rowBase + wm * 32 + i * 16 + g4;
            #pragma unroll
            for (int j = 0; j < 8; ++j) {
                int col = wn * 64 + j * 8 + q * 2;
                __nv_bfloat162 p0(__float2bfloat16(acc[i][j][0]), __float2bfloat16(acc[i][j][1]));
                __nv_bfloat162 p1(__float2bfloat16(acc[i][j][2]), __float2bfloat16(acc[i][j][3]));
                if (r0 < M)
                    *(__nv_bfloat162*)(C + (size_t)r0 * 128 + col) = p0;
                if (r0 + 8 < M)
                    *(__nv_bfloat162*)(C + (size_t)(r0 + 8) * 128 + col) = p1;
            }
        }
    }
}

// ---------------- head ----------------
__global__ void head_kernel(const float* __restrict__ pooled,
                            const float* __restrict__ w1, const float* __restrict__ b1,
                            const float* __restrict__ w2, const float* __restrict__ b2,
                            float* __restrict__ out)
{
    __shared__ float t[NGRAPH][HID];
    int tid = threadIdx.x;
    for (int o = tid; o < NGRAPH * HID; o += blockDim.x) {
        int r = o >> 7, c = o & 127;
        float s = b1[c];
        #pragma unroll 8
        for (int k = 0; k < 128; ++k) s = fmaf(pooled[r * 128 + k], w1[k * 128 + c], s);
        t[r][c] = s;
    }
    __syncthreads();
    if (tid < NGRAPH) {
        float z0 = b2[0], z1 = b2[1];
        #pragma unroll 8
        for (int k = 0; k < 128; ++k) {
            float v = t[tid][k];
            z0 = fmaf(v, w2[k * 2 + 0], z0);
            z1 = fmaf(v, w2[k * 2 + 1], z1);
        }
        float m = fmaxf(z0, z1);
        float lse = m + logf(expf(z0 - m) + expf(z1 - m));
        out[tid * 2 + 0] = z0 - lse;
        out[tid * 2 + 1] = z1 - lse;
    }
}

// ---------------- launch ----------------
static cudaStream_t g_s2 = nullptr;
static cudaEvent_t  g_e1 = nullptr, g_e2 = nullptr;

extern "C" void kernel_launch(void* const* d_in, const int* in_sizes, int n_in,
                              void* d_out, int out_size)
{
    const float* x      = (const float*)d_in[0];
    const int*   ei     = (const int*)  d_in[1];
    const int*   batch  = (const int*)  d_in[2];
    const float* lin_w0 = (const float*)d_in[3];
    const float* lin_b0 = (const float*)d_in[4];
    const float* agg_w0 = (const float*)d_in[5];
    const float* agg_b0 = (const float*)d_in[6];
    const float* lin_w1 = (const float*)d_in[7];
    const float* lin_b1 = (const float*)d_in[8];
    const float* agg_w1 = (const float*)d_in[9];
    const float* agg_b1 = (const float*)d_in[10];
    const float* mp_w1  = (const float*)d_in[11];
    const float* mp_b1  = (const float*)d_in[12];
    const float* mp_w2  = (const float*)d_in[13];
    const float* mp_b2  = (const float*)d_in[14];
    float* out = (float*)d_out;

    const int N = in_sizes[0] / HID;
    const int E = in_sizes[1] / 2;
    const int* src = ei;
    const int* dst = ei + E;

    if (!g_s2) {
        cudaStreamCreateWithFlags(&g_s2, cudaStreamNonBlocking);
        cudaEventCreateWithFlags(&g_e1, cudaEventDisableTiming);
        cudaEventCreateWithFlags(&g_e2, cudaEventDisableTiming);
    }

    void *p;
    float *pooled;
    int *cnt, *off, *fill, *srcs, *bsum;
    __nv_bfloat16 *xb, *yb, *h0b, *wt;
    cudaGetSymbolAddress(&p, g_pooled); pooled = (float*)p;
    cudaGetSymbolAddress(&p, g_cnt);    cnt    = (int*)p;
    cudaGetSymbolAddress(&p, g_off);    off    = (int*)p;
    cudaGetSymbolAddress(&p, g_fill);   fill   = (int*)p;
    cudaGetSymbolAddress(&p, g_srcs);   srcs   = (int*)p;
    cudaGetSymbolAddress(&p, g_bsum);   bsum   = (int*)p;
    cudaGetSymbolAddress(&p, g_xb);     xb     = (__nv_bfloat16*)p;
    cudaGetSymbolAddress(&p, g_yb);     yb     = (__nv_bfloat16*)p;
    cudaGetSymbolAddress(&p, g_h0b);    h0b    = (__nv_bfloat16*)p;
    cudaGetSymbolAddress(&p, g_wt);     wt     = (__nv_bfloat16*)p;

    cudaFuncSetAttribute(gemm_mma, cudaFuncAttributeMaxDynamicSharedMemorySize, SMEM_GEMM);

    const int nTiles = (N + 127) / 128;
    const int Ntot = N + 1;
    const int nScanB = (Ntot + 1023) / 1024;
    const int zeroN = (Ntot > NGRAPH * HID) ? Ntot : NGRAPH * HID;

    cudaEventRecord(g_e1, 0);

    // ---- default stream: converts + lin0 ----
    {
        dim3 g((128 * 256 + 255) / 256, 4);
        wconvert_all<<<g, 256>>>(lin_w0, agg_w0, lin_w1, agg_w1, wt);
    }
    xconvert_kernel<<<(N * 32 + 255) / 256, 256>>>(x, xb, N * 32);
    gemm_mma<<<nTiles, 256, SMEM_GEMM>>>(nullptr, xb, wt, 128, lin_b0,
                                         yb, nullptr, nullptr, nullptr, nullptr, N, 0);

    // ---- stream 2: CSR build + zero pool ----
    cudaStreamWaitEvent(g_s2, g_e1, 0);
    zero_kernel<<<(zeroN + 255) / 256, 256, 0, g_s2>>>(cnt, pooled, Ntot, NGRAPH * HID);
    hist_kernel<<<(E + 255) / 256, 256, 0, g_s2>>>(dst, cnt, E);
    scan1_kernel<<<nScanB, 1024, 0, g_s2>>>(cnt, bsum, Ntot);
    scan2_kernel<<<1, 32, 0, g_s2>>>(bsum, nScanB);
    scan3_kernel<<<nScanB, 1024, 0, g_s2>>>(cnt, bsum, off, fill, Ntot, N);
    fill_kernel<<<(E + 255) / 256, 256, 0, g_s2>>>(src, dst, fill, srcs, E);
    cudaEventRecord(g_e2, g_s2);

    cudaStreamWaitEvent(0, g_e2, 0);

    // layer 0: fused agg(yb) + concat GEMM -> h0b (norm)
    gemm_mma<<<nTiles, 256, SMEM_GEMM>>>(yb, xb, wt + 16384, 256, agg_b0,
                                         h0b, off, srcs, nullptr, nullptr, N, 1);
    // layer 1: lin1 then fused agg(yb) + concat GEMM -> pool
    gemm_mma<<<nTiles, 256, SMEM_GEMM>>>(nullptr, h0b, wt + 49152, 128, lin_b1,
                                         yb, nullptr, nullptr, nullptr, nullptr, N, 0);
    gemm_mma<<<nTiles, 256, SMEM_GEMM>>>(yb, h0b, wt + 65536, 256, agg_b1,
                                         nullptr, off, srcs, batch, pooled, N, 1);

    head_kernel<<<1, 256>>>(pooled, mp_w1, mp_b1, mp_w2, mp_b2, out);
}